// round 14
// baseline (speedup 1.0000x reference)
#include <cuda_runtime.h>
#include <cuda_bf16.h>
#include <math_constants.h>

// Problem constants (fixed by the reference)
#define BB     2
#define HH     112
#define WW     112
#define HW     (HH * WW)        // 12544
#define NPIX   (BB * HW)        // 25088
#define SEG_T  0.7f
#define EPS_K  1e-7f
// Output nonzero requires q <= eps - ln(0.7) = 0.3566750.
#define Q_RAD  0.36f
#define Q_CUT  0.37f

// 7x7 tiles of 16x16 per image; 98 blocks; 1024 threads = one per region pt.
#define TILE   16
#define TPS    7
#define HALO   8                 // R<=8 <=> maxvar<=88.9 <=> |v|<=9.43
#define REG    32                // TILE + 2*HALO
#define NTHR   1024
#define FULL   0xFFFFFFFFu

// floor(65536/w)+1 for w = 2R+1, R = 1..8  (exact cell/w for cell < 289)
__constant__ int c_magic[8] = {21846, 13108, 9363, 7282, 5958, 5042, 4370, 3856};

__global__ void __launch_bounds__(NTHR, 1)
k_one(const float* __restrict__ variance,
      const float* __restrict__ center,
      float* __restrict__ out, int out_size)
{
    __shared__ unsigned int qmin[TILE * TILE];

    const int tid = threadIdx.x;
    const int blk = blockIdx.x;
    const int b   = blk / (TPS * TPS);
    const int t   = blk - b * (TPS * TPS);
    const int tr  = (t / TPS) * TILE;
    const int tc  = (t % TPS) * TILE;

    const float* varb = variance + (size_t)b * 3 * HW;
    const float* cenb = center   + (size_t)b * HW;

    // ---- Loads first, unconditional (clamped addr), so all 4 are in flight
    // across the barrier below. warp id == region row -> warp-uniform rows.
    const int lr = tid >> 5;
    const int lc = tid & 31;
    const int pr = tr - HALO + lr;
    const int pc = tc - HALO + lc;
    const bool inb = (pr >= 0) & (pr < HH) & (pc >= 0) & (pc < WW);
    const int prc = min(max(pr, 0), HH - 1);
    const int pcc = min(max(pc, 0), WW - 1);
    const int pixc = prc * WW + pcc;

    float cm = cenb[pixc];
    float a0 = varb[pixc];
    float a1 = varb[HW + pixc];
    float a2 = varb[2 * HW + pixc];

    if (tid < TILE * TILE) qmin[tid] = 0x7F800000u;   // +inf

    __syncthreads();   // qmin init visible before any scatter (overlaps loads)

    float mask = (inb && (cm > SEG_T)) ? 1.0f : 0.0f;
    float vx = a0 * mask;
    float vy = a1 * mask;
    // sel = (vx + vy) != 0  (matches torch.nonzero(vx+vy) semantics)
    const bool sel = inb && ((vx + vy) != 0.0f);

    // ---- Inline coefficients on selected lanes (math order identical to the
    // validated kernel; q downstream is bit-identical).
    float Av = 0.0f, B2v = 0.0f, Cv = 0.0f;
    int   pack = 0;
    if (sel) {
        float theta = 3.14f * (1.0f / (1.0f + expf(-a2)));
        float s, c;
        sincosf(theta, &s, &c);

        float var_x = vx * vx + EPS_K;
        float var_y = vy * vy + EPS_K;

        float inv2x = 1.0f / (2.0f * var_x);
        float inv2y = 1.0f / (2.0f * var_y);

        Av  = c * c * inv2x + s * s * inv2y;
        Cv  = s * s * inv2x + c * c * inv2y;
        B2v = 2.0f * (-2.0f * s * c / (4.0f * var_x)
                      + 2.0f * s * c / (4.0f * var_y));

        float maxvar = fmaxf(var_x, var_y);
        int R = (int)floorf(sqrtf(2.0f * maxvar * Q_RAD)) + 1;   // 1..8
        R = min(R, HALO);
        int mg = c_magic[R - 1];

        // pack: magic[16] | R[5] | (lpr+8)[5] | (lpc+8)[5]
        pack = (mg << 16) | (R << 10) | ((pr - tr + 8) << 5) | (pc - tc + 8);
    }

    // ---- Per-warp shuffle scatter: loop over this warp's selected lanes;
    // 32 lanes cover each point's (2R+1)^2 box cells in parallel.
    {
        const int lane = tid & 31;
        unsigned mbits = __ballot_sync(FULL, sel);
        while (mbits) {
            int k = __ffs(mbits) - 1;
            mbits &= mbits - 1;

            float A  = __shfl_sync(FULL, Av,  k);
            float B2 = __shfl_sync(FULL, B2v, k);
            float C  = __shfl_sync(FULL, Cv,  k);
            int   pk = __shfl_sync(FULL, pack, k);

            int mg  = (int)((unsigned)pk >> 16);
            int R   = (pk >> 10) & 31;
            int lpr = ((pk >> 5) & 31) - 8;
            int lpc = (pk & 31) - 8;
            int w   = 2 * R + 1;
            int cells = w * w;

            for (int cell = lane; cell < cells; cell += 32) {
                int dy = (cell * mg) >> 16;      // cell / w (exact)
                int dx = cell - dy * w;
                int i  = lpr + dy - R;
                int j  = lpc + dx - R;
                if ((unsigned)i < (unsigned)TILE &&
                    (unsigned)j < (unsigned)TILE) {
                    float di  = (float)(dy - R);
                    float dj  = (float)(dx - R);
                    float adi = A * di * di;     // same op order as before
                    float bdi = B2 * di;
                    float q   = fmaf(C * dj + bdi, dj, adi);
                    if (q <= Q_CUT) {
                        atomicMin(&qmin[i * TILE + j], __float_as_uint(q));
                    }
                }
            }
        }
    }

    __syncthreads();

    // ---- Finalize this tile (threads 0..255 own one pixel each).
    if (tid < TILE * TILE) {
        int oy = tid >> 4;
        int ox = tid & (TILE - 1);
        float q = __uint_as_float(qmin[tid]);
        float g = expf(-q + EPS_K);            // q=+inf -> g=0
        out[(size_t)b * HW + (tr + oy) * WW + (tc + ox)] =
            (g >= 0.7f) ? g : 0.0f;
    }

    // Zero-fill any trailing output elements (the `flag` scalar).
    if (blk == 0 && tid == 0) {
        for (int o = NPIX; o < out_size; ++o) out[o] = 0.0f;
    }
}

// ---------------------------------------------------------------------------
// Inputs (metadata order): x[2,32,112,112], variance[2,3,112,112],
// center_map[2,1,112,112], conv_w[1,32], conv_b[1].
// x / conv_w / conv_b are dead in the reference (threshold branch unused).
// ---------------------------------------------------------------------------
extern "C" void kernel_launch(void* const* d_in, const int* in_sizes, int n_in,
                              void* d_out, int out_size)
{
    const float* variance = (const float*)d_in[1];
    const float* center   = (const float*)d_in[2];
    float*       out      = (float*)d_out;

    k_one<<<BB * TPS * TPS, NTHR>>>(variance, center, out, out_size);
}

// round 15
// speedup vs baseline: 1.0238x; 1.0238x over previous
#include <cuda_runtime.h>
#include <cuda_bf16.h>
#include <math_constants.h>

// Problem constants (fixed by the reference)
#define BB     2
#define HH     112
#define WW     112
#define HW     (HH * WW)        // 12544
#define NPIX   (BB * HW)        // 25088
#define SEG_T  0.7f
#define EPS_K  1e-7f
// Output nonzero requires q <= eps - ln(0.7) = 0.3566750.
#define Q_RAD  0.36f
#define Q_CUT  0.37f

// 7x7 tiles of 16x16 per image; 98 blocks; 1024 threads = one per region pt.
#define TILE   16
#define TPS    7
#define HALO   8                 // R<=8 <=> maxvar<=88.9 <=> |v|<=9.43
#define REG    32                // TILE + 2*HALO
#define NTHR   1024
#define FULL   0xFFFFFFFFu

// floor(65536/w)+1 for w = 2R+1, R = 1..8  (exact cell/w for cell < 289)
__constant__ int c_magic[8] = {21846, 13108, 9363, 7282, 5958, 5042, 4370, 3856};

__global__ void __launch_bounds__(NTHR, 1)
k_one(const float* __restrict__ variance,
      const float* __restrict__ center,
      float* __restrict__ out, int out_size)
{
    __shared__ unsigned int qmin[TILE * TILE];

    const int tid = threadIdx.x;
    const int blk = blockIdx.x;
    const int b   = blk / (TPS * TPS);
    const int t   = blk - b * (TPS * TPS);
    const int tr  = (t / TPS) * TILE;
    const int tc  = (t % TPS) * TILE;

    const float* varb = variance + (size_t)b * 3 * HW;
    const float* cenb = center   + (size_t)b * HW;

    // ---- Loads first, unconditional (clamped addr), so all 4 are in flight
    // across the barrier below. warp id == region row -> warp-uniform rows.
    const int lr = tid >> 5;
    const int lc = tid & 31;
    const int pr = tr - HALO + lr;
    const int pc = tc - HALO + lc;
    const bool inb = (pr >= 0) & (pr < HH) & (pc >= 0) & (pc < WW);
    const int prc = min(max(pr, 0), HH - 1);
    const int pcc = min(max(pc, 0), WW - 1);
    const int pixc = prc * WW + pcc;

    float cm = cenb[pixc];
    float a0 = varb[pixc];
    float a1 = varb[HW + pixc];
    float a2 = varb[2 * HW + pixc];

    if (tid < TILE * TILE) qmin[tid] = 0x7F800000u;   // +inf

    __syncthreads();   // qmin init visible before any scatter (overlaps loads)

    float mask = (inb && (cm > SEG_T)) ? 1.0f : 0.0f;
    float vx = a0 * mask;
    float vy = a1 * mask;
    // sel = (vx + vy) != 0  (matches torch.nonzero(vx+vy) semantics)
    const bool sel = inb && ((vx + vy) != 0.0f);

    // ---- Inline coefficients on selected lanes (math order identical to the
    // validated kernel; q downstream is bit-identical).
    float Av = 0.0f, B2v = 0.0f, Cv = 0.0f;
    int   pack = 0;
    if (sel) {
        float theta = 3.14f * (1.0f / (1.0f + expf(-a2)));
        float s, c;
        sincosf(theta, &s, &c);

        float var_x = vx * vx + EPS_K;
        float var_y = vy * vy + EPS_K;

        float inv2x = 1.0f / (2.0f * var_x);
        float inv2y = 1.0f / (2.0f * var_y);

        Av  = c * c * inv2x + s * s * inv2y;
        Cv  = s * s * inv2x + c * c * inv2y;
        B2v = 2.0f * (-2.0f * s * c / (4.0f * var_x)
                      + 2.0f * s * c / (4.0f * var_y));

        float maxvar = fmaxf(var_x, var_y);
        int R = (int)floorf(sqrtf(2.0f * maxvar * Q_RAD)) + 1;   // 1..8
        R = min(R, HALO);
        int mg = c_magic[R - 1];

        // pack: magic[16] | R[5] | (lpr+8)[5] | (lpc+8)[5]
        pack = (mg << 16) | (R << 10) | ((pr - tr + 8) << 5) | (pc - tc + 8);
    }

    // ---- Per-warp shuffle scatter: loop over this warp's selected lanes;
    // 32 lanes cover each point's (2R+1)^2 box cells in parallel.
    {
        const int lane = tid & 31;
        unsigned mbits = __ballot_sync(FULL, sel);
        while (mbits) {
            int k = __ffs(mbits) - 1;
            mbits &= mbits - 1;

            float A  = __shfl_sync(FULL, Av,  k);
            float B2 = __shfl_sync(FULL, B2v, k);
            float C  = __shfl_sync(FULL, Cv,  k);
            int   pk = __shfl_sync(FULL, pack, k);

            int mg  = (int)((unsigned)pk >> 16);
            int R   = (pk >> 10) & 31;
            int lpr = ((pk >> 5) & 31) - 8;
            int lpc = (pk & 31) - 8;
            int w   = 2 * R + 1;
            int cells = w * w;

            for (int cell = lane; cell < cells; cell += 32) {
                int dy = (cell * mg) >> 16;      // cell / w (exact)
                int dx = cell - dy * w;
                int i  = lpr + dy - R;
                int j  = lpc + dx - R;
                if ((unsigned)i < (unsigned)TILE &&
                    (unsigned)j < (unsigned)TILE) {
                    float di  = (float)(dy - R);
                    float dj  = (float)(dx - R);
                    float adi = A * di * di;     // same op order as before
                    float bdi = B2 * di;
                    float q   = fmaf(C * dj + bdi, dj, adi);
                    if (q <= Q_CUT) {
                        atomicMin(&qmin[i * TILE + j], __float_as_uint(q));
                    }
                }
            }
        }
    }

    __syncthreads();

    // ---- Finalize this tile (threads 0..255 own one pixel each).
    if (tid < TILE * TILE) {
        int oy = tid >> 4;
        int ox = tid & (TILE - 1);
        float q = __uint_as_float(qmin[tid]);
        float g = expf(-q + EPS_K);            // q=+inf -> g=0
        out[(size_t)b * HW + (tr + oy) * WW + (tc + ox)] =
            (g >= 0.7f) ? g : 0.0f;
    }

    // Zero-fill any trailing output elements (the `flag` scalar).
    if (blk == 0 && tid == 0) {
        for (int o = NPIX; o < out_size; ++o) out[o] = 0.0f;
    }
}

// ---------------------------------------------------------------------------
// Inputs (metadata order): x[2,32,112,112], variance[2,3,112,112],
// center_map[2,1,112,112], conv_w[1,32], conv_b[1].
// x / conv_w / conv_b are dead in the reference (threshold branch unused).
// ---------------------------------------------------------------------------
extern "C" void kernel_launch(void* const* d_in, const int* in_sizes, int n_in,
                              void* d_out, int out_size)
{
    const float* variance = (const float*)d_in[1];
    const float* center   = (const float*)d_in[2];
    float*       out      = (float*)d_out;

    k_one<<<BB * TPS * TPS, NTHR>>>(variance, center, out, out_size);
}